// round 10
// baseline (speedup 1.0000x reference)
#include <cuda_runtime.h>
#include <cuda_fp16.h>
#include <cstdint>

#define IN_F   4096
#define OUT_F  4096
#define MTOT   8192
#define RANK   16
#define QBLOCK 64
#define SCALING 2.0f

// Two device passes: compute_103 (PTX, no tcgen05, compile-only fallback) and
// sm_103a (SASS, tcgen05 — this is the cubin that executes).
#if defined(__CUDA_ARCH_FEAT_SM103_ALL) || defined(__CUDA_ARCH_FEAT_SM100_ALL)
#define HAS_TCGEN05 1
#else
#define HAS_TCGEN05 0
#endif

// Scratch (allocation-free rule: __device__ globals)
__device__ __half g_X[(size_t)MTOT * IN_F];    // 64 MB fp16 activations
__device__ __half g_W[(size_t)OUT_F * IN_F];   // 32 MB fp16 effective weight

// ---------------------------------------------------------------------------
// Kernel 0: no-op — keeps ncu's sampled launch on the GEMM.
// ---------------------------------------------------------------------------
__global__ void k_sample_shift() {}

// ---------------------------------------------------------------------------
// Kernel 1: convert x (fp32 -> fp16)  — 28us, HBM-bound.
// ---------------------------------------------------------------------------
__global__ void k_convert_x(const float* __restrict__ x) {
    size_t idx  = (size_t)blockIdx.x * blockDim.x + threadIdx.x;
    size_t base = idx * 8;
    const float4* xv = reinterpret_cast<const float4*>(x + base);
    float4 a = xv[0];
    float4 b = xv[1];
    __half2 h0 = __floats2half2_rn(a.x, a.y);
    __half2 h1 = __floats2half2_rn(a.z, a.w);
    __half2 h2 = __floats2half2_rn(b.x, b.y);
    __half2 h3 = __floats2half2_rn(b.z, b.w);
    uint4 o;
    o.x = *reinterpret_cast<unsigned*>(&h0);
    o.y = *reinterpret_cast<unsigned*>(&h1);
    o.z = *reinterpret_cast<unsigned*>(&h2);
    o.w = *reinterpret_cast<unsigned*>(&h3);
    reinterpret_cast<uint4*>(g_X)[idx] = o;
}

// ---------------------------------------------------------------------------
// Kernel 2: W_eff = dequant(q,scales) + SCALING * B@A  (fp16 out)
// ---------------------------------------------------------------------------
__global__ void k_build_w(const int*   __restrict__ q,
                          const float* __restrict__ sc,
                          const float* __restrict__ A,
                          const float* __restrict__ B) {
    __shared__ __align__(16) float Ash[RANK][512];   // 32 KB
    __shared__ __align__(16) float Bsh[128][16];     // 8 KB
    __shared__ float Ssh[128][8];                    // 4 KB

    const int t  = threadIdx.x;            // 256 threads
    const int i0 = blockIdx.x * 512;
    const int o0 = blockIdx.y * 128;

    #pragma unroll
    for (int j = 0; j < 8; j++) {
        int idx = t + 256 * j;
        int r   = idx >> 7;
        int c4  = idx & 127;
        float4 v = reinterpret_cast<const float4*>(A + (size_t)r * IN_F + i0)[c4];
        *reinterpret_cast<float4*>(&Ash[r][c4 * 4]) = v;
    }
    #pragma unroll
    for (int j = 0; j < 8; j++) {
        int idx = t + 256 * j;
        int o   = idx >> 4;
        int r   = idx & 15;
        Bsh[o][r] = B[(size_t)(o0 + o) * RANK + r] * SCALING;
    }
    if (t < 128) {
        #pragma unroll
        for (int blk = 0; blk < 8; blk++)
            Ssh[t][blk] = sc[(size_t)(o0 + t) * (IN_F / QBLOCK) + (i0 >> 6) + blk];
    }
    __syncthreads();

    const int lane = t & 31;
    const int wid  = t >> 5;

    #pragma unroll
    for (int j = 0; j < 4; j++) {
        const int il = (j * 32 + lane) * 4;
        float4 a[RANK];
        #pragma unroll
        for (int r = 0; r < RANK; r++)
            a[r] = *reinterpret_cast<const float4*>(&Ash[r][il]);

        #pragma unroll 2
        for (int oo = 0; oo < 16; oo++) {
            const int    ol   = (wid << 4) + oo;
            const int    o    = o0 + ol;
            const size_t orow = (size_t)o * IN_F;
            const int4   q4   = *reinterpret_cast<const int4*>(q + orow + i0 + il);
            const float  s    = Ssh[ol][il >> 6];

            float4 acc;
            acc.x = (float)(q4.x - 8) * s;
            acc.y = (float)(q4.y - 8) * s;
            acc.z = (float)(q4.z - 8) * s;
            acc.w = (float)(q4.w - 8) * s;

            const float4 b0 = *reinterpret_cast<const float4*>(&Bsh[ol][0]);
            const float4 b1 = *reinterpret_cast<const float4*>(&Bsh[ol][4]);
            const float4 b2 = *reinterpret_cast<const float4*>(&Bsh[ol][8]);
            const float4 b3 = *reinterpret_cast<const float4*>(&Bsh[ol][12]);
            const float bb[16] = { b0.x,b0.y,b0.z,b0.w, b1.x,b1.y,b1.z,b1.w,
                                   b2.x,b2.y,b2.z,b2.w, b3.x,b3.y,b3.z,b3.w };
            #pragma unroll
            for (int r = 0; r < RANK; r++) {
                acc.x += bb[r] * a[r].x;
                acc.y += bb[r] * a[r].y;
                acc.z += bb[r] * a[r].z;
                acc.w += bb[r] * a[r].w;
            }
            __half2 h0 = __floats2half2_rn(acc.x, acc.y);
            __half2 h1 = __floats2half2_rn(acc.z, acc.w);
            uint2 st;
            st.x = *reinterpret_cast<unsigned*>(&h0);
            st.y = *reinterpret_cast<unsigned*>(&h1);
            *reinterpret_cast<uint2*>(g_W + orow + i0 + il) = st;
        }
    }
}

// ---------------------------------------------------------------------------
// Kernel 3: GEMM out[M,N] = Xh[M,K] @ W[N,K]^T + bias.  grid (16,64), 256 thr.
//   tcgen05 path (EXECUTES): CTA tile 128x256, 4-stage ring, WARP-SPECIALIZED:
//     consumer = thread 0 (mbar waits + MMA issue + commit only),
//     producers = warps 1-7 (cp.async fills, completion via
//     cp.async.mbarrier.arrive.noinc).  NO __syncthreads in the main loop.
//   HMMA fallback (#else): compile-only for the compute_103 PTX pass.
// ---------------------------------------------------------------------------
#define TC_NSTAGE   4
#define TC_STAGE    49152u             // 128 A rows + 256 B rows, 128B each
#define FB_NSTAGE   3
#define FB_STAGE    49152u
#define SMEM_DYN    (2048 + 4 * 49152)
#define IDESC       0x8400010u         // F32 D, F16 A/B, N=256, M=128
#define NPROD       224                // producer threads (warps 1-7)

// SW128 K-major smem descriptor base (layout=2, ver=1, SBO=64, LBO=1)
#define DESC_BASE ( (2ull << 61) | (1ull << 46) | (64ull << 32) | (1ull << 16) )
#define MAKE_DESC(addr) (DESC_BASE | ((uint64_t)((addr) >> 4) & 0x3FFF))

__device__ __forceinline__ uint32_t smem_u32(const void* p) {
    uint32_t a;
    asm("{ .reg .u64 t; cvta.to.shared.u64 t, %1; cvt.u32.u64 %0, t; }"
        : "=r"(a) : "l"(p));
    return a;
}

__device__ __forceinline__ void cp16(uint32_t smem, const void* gmem) {
    asm volatile("cp.async.cg.shared.global [%0], [%1], 16;\n"
                 :: "r"(smem), "l"(gmem) : "memory");
}

#if HAS_TCGEN05
__device__ __forceinline__ void mma_f16_ss(uint32_t d, uint64_t ad, uint64_t bd,
                                           uint32_t en) {
    asm volatile(
        "{\n\t"
        ".reg .pred p;\n\t"
        "setp.ne.u32 p, %4, 0;\n\t"
        "tcgen05.mma.cta_group::1.kind::f16 [%0], %1, %2, %3, {%5,%5,%5,%5}, p;\n\t"
        "}"
        :: "r"(d), "l"(ad), "l"(bd), "r"(IDESC), "r"(en), "r"(0u) : "memory");
}
__device__ __forceinline__ void mbar_init(uint32_t mb, uint32_t cnt) {
    asm volatile("mbarrier.init.shared.b64 [%0], %1;" :: "r"(mb), "r"(cnt) : "memory");
}
__device__ __forceinline__ void mbar_wait(uint32_t mb, uint32_t parity) {
    asm volatile(
        "{\n\t"
        ".reg .pred P;\n\t"
        "LAB_WAIT_%=:\n\t"
        "mbarrier.try_wait.parity.acquire.cta.shared::cta.b64 P, [%0], %1, 0x989680;\n\t"
        "@P bra.uni LAB_DONE_%=;\n\t"
        "bra.uni LAB_WAIT_%=;\n\t"
        "LAB_DONE_%=:\n\t"
        "}"
        :: "r"(mb), "r"(parity) : "memory");
}
__device__ __forceinline__ void cpasync_arrive_noinc(uint32_t mb) {
    asm volatile("cp.async.mbarrier.arrive.noinc.shared.b64 [%0];"
                 :: "r"(mb) : "memory");
}
#endif

__global__ void __launch_bounds__(256, 1) k_gemm(const float* __restrict__ bias,
                                                 float* __restrict__ out) {
    extern __shared__ char smem[];
    const uint32_t smem_base = smem_u32(smem);
    const uint32_t tiles = (smem_base + 72 + 1023) & ~1023u;

    const int t    = threadIdx.x;
    const int lane = t & 31;
    const int wid  = t >> 5;

#if HAS_TCGEN05
    // ======================= tcgen05 path (EXECUTES) =======================
    const int m0 = blockIdx.y * 128;
    const int n0 = blockIdx.x * 256;

    // mbarriers: full[s] at +8..+32 (count=NPROD), mma_done[s] at +40..+64 (count=1)
    const uint32_t mb_full = smem_base + 8;
    const uint32_t mb_done = smem_base + 40;

    if (wid == 0) {
        asm volatile("tcgen05.alloc.cta_group::1.sync.aligned.shared::cta.b32 [%0], %1;"
                     :: "r"(smem_base), "r"(256u) : "memory");
        asm volatile("tcgen05.relinquish_alloc_permit.cta_group::1.sync.aligned;");
    }
    if (t == 0) {
        #pragma unroll
        for (int s = 0; s < 4; s++) {
            mbar_init(mb_full + s * 8, NPROD);
            mbar_init(mb_done + s * 8, 1);
        }
    }
    __syncthreads();
    uint32_t tmem;
    asm volatile("ld.shared.b32 %0, [%1];" : "=r"(tmem) : "r"(smem_base));

    const __half* gA = g_X + (size_t)m0 * IN_F;
    const __half* gB = g_W + (size_t)n0 * IN_F;

    const int KT = IN_F / 64;   // 64 chunks

    if (t == 0) {
        // ---------------- consumer: MMA issue only ----------------
        for (int c = 0; c < KT; c++) {
            const int slot = c & 3;
            mbar_wait(mb_full + slot * 8, (c >> 2) & 1);
            asm volatile("fence.proxy.async.shared::cta;" ::: "memory");
            const uint32_t sb = tiles + (uint32_t)slot * TC_STAGE;
            const uint64_t ad = MAKE_DESC(sb);
            const uint64_t bd = MAKE_DESC(sb + 16384u);
            #pragma unroll
            for (int j = 0; j < 4; j++)
                mma_f16_ss(tmem, ad + j * 2, bd + j * 2, (c > 0 || j > 0) ? 1u : 0u);
            asm volatile(
                "tcgen05.commit.cta_group::1.mbarrier::arrive::one.shared::cluster.b64 [%0];"
                :: "r"(mb_done + slot * 8) : "memory");
        }
    } else if (wid >= 1) {
        // ---------------- producers: fills only ----------------
        const int p = t - 32;              // 0..223
        for (int f = 0; f < KT; f++) {
            const int slot = f & 3;
            if (f >= 4) {
                // stage slot last read by MMA chunk f-4 (occupant (f>>2)-1)
                mbar_wait(mb_done + slot * 8, ((f >> 2) - 1) & 1);
            }
            const uint32_t sb   = tiles + (uint32_t)slot * TC_STAGE;
            const int      koff = f * 64;
            for (int i = p; i < 3072; i += NPROD) {
                if (i < 1024) {            // A tile: 128 rows x 8 chunks
                    const int row = i >> 3;
                    const int cc  = i & 7;
                    cp16(sb + (uint32_t)row * 128 + ((uint32_t)(cc ^ (row & 7)) << 4),
                         gA + (size_t)row * IN_F + koff + cc * 8);
                } else {                   // B tile: 256 rows x 8 chunks
                    const int j2  = i - 1024;
                    const int row = j2 >> 3;
                    const int cc  = j2 & 7;
                    cp16(sb + 16384u + (uint32_t)row * 128 +
                             ((uint32_t)(cc ^ (row & 7)) << 4),
                         gB + (size_t)row * IN_F + koff + cc * 8);
                }
            }
            cpasync_arrive_noinc(mb_full + slot * 8);
        }
    }

    // all threads: wait for final MMA chunk (c=63 -> slot 3, occupant 15)
    mbar_wait(mb_done + ((KT - 1) & 3) * 8, ((KT - 1) >> 2) & 1);
    asm volatile("tcgen05.fence::after_thread_sync;" ::: "memory");

    // Epilogue: 8 warps = (subpartition wid&3) x (col-half wid>>2)
    {
        const int subp  = wid & 3;
        const int chalf = wid >> 2;
        const int m     = m0 + subp * 32 + lane;
        const int cbase = chalf * 128;
        float* orow     = out + (size_t)m * OUT_F + n0 + cbase;
        const uint32_t dbase = tmem + cbase;

        #pragma unroll
        for (int cc = 0; cc < 4; cc++) {
            uint32_t r[32];
            asm volatile(
                "tcgen05.ld.sync.aligned.32x32b.x32.b32 "
                "{%0,%1,%2,%3,%4,%5,%6,%7,%8,%9,%10,%11,%12,%13,%14,%15,"
                "%16,%17,%18,%19,%20,%21,%22,%23,%24,%25,%26,%27,%28,%29,%30,%31}, [%32];"
                : "=r"(r[0]),  "=r"(r[1]),  "=r"(r[2]),  "=r"(r[3]),
                  "=r"(r[4]),  "=r"(r[5]),  "=r"(r[6]),  "=r"(r[7]),
                  "=r"(r[8]),  "=r"(r[9]),  "=r"(r[10]), "=r"(r[11]),
                  "=r"(r[12]), "=r"(r[13]), "=r"(r[14]), "=r"(r[15]),
                  "=r"(r[16]), "=r"(r[17]), "=r"(r[18]), "=r"(r[19]),
                  "=r"(r[20]), "=r"(r[21]), "=r"(r[22]), "=r"(r[23]),
                  "=r"(r[24]), "=r"(r[25]), "=r"(r[26]), "=r"(r[27]),
                  "=r"(r[28]), "=r"(r[29]), "=r"(r[30]), "=r"(r[31])
                : "r"(dbase + cc * 32));
            asm volatile("tcgen05.wait::ld.sync.aligned;" ::: "memory");

            const float4* bv = reinterpret_cast<const float4*>(bias + n0 + cbase + cc * 32);
            float4* ov = reinterpret_cast<float4*>(orow + cc * 32);
            #pragma unroll
            for (int v = 0; v < 8; v++) {
                float4 b4 = bv[v];
                float4 o4;
                o4.x = __uint_as_float(r[4 * v + 0]) + b4.x;
                o4.y = __uint_as_float(r[4 * v + 1]) + b4.y;
                o4.z = __uint_as_float(r[4 * v + 2]) + b4.z;
                o4.w = __uint_as_float(r[4 * v + 3]) + b4.w;
                ov[v] = o4;
            }
        }
    }
    __syncthreads();
    if (wid == 0) {
        asm volatile("tcgen05.dealloc.cta_group::1.sync.aligned.b32 %0, %1;"
                     :: "r"(tmem), "r"(256u));
    }
#else
    // ============== HMMA fallback (compile-only on compute_103) ==========
    const int m0 = blockIdx.y * 128;
    const int n0 = blockIdx.x * 256;
    const int wm = wid & 1;
    const int wn = wid >> 1;

    const int r0   = t >> 3;
    const int csrc = (t & 7) * 8;
    const uint32_t chs = (uint32_t)(((t & 7) ^ (r0 & 7)) << 4);

    const __half* gA = g_X + (size_t)m0 * IN_F;
    const __half* gB = g_W + (size_t)n0 * IN_F;

    auto fillf = [&](int f) {
        const uint32_t sb   = tiles + (uint32_t)(f % FB_NSTAGE) * FB_STAGE;
        const int      koff = f * 64;
        #pragma unroll
        for (int j = 0; j < 4; j++) {
            int row = r0 + 32 * j;
            cp16(sb + (uint32_t)row * 128 + chs,
                 gA + (size_t)row * IN_F + koff + csrc);
        }
        #pragma unroll
        for (int j = 0; j < 8; j++) {
            int row = r0 + 32 * j;
            cp16(sb + 16384u + (uint32_t)row * 128 + chs,
                 gB + (size_t)row * IN_F + koff + csrc);
        }
    };

    float acc[4][8][4];
    #pragma unroll
    for (int i = 0; i < 4; i++)
        #pragma unroll
        for (int j = 0; j < 8; j++)
            #pragma unroll
            for (int k = 0; k < 4; k++) acc[i][j][k] = 0.f;

    fillf(0);
    asm volatile("cp.async.commit_group;\n" ::: "memory");
    fillf(1);
    asm volatile("cp.async.commit_group;\n" ::: "memory");
    fillf(2);
    asm volatile("cp.async.commit_group;\n" ::: "memory");

    for (int c = 0; c < 64; c++) {
        asm volatile("cp.async.wait_group 2;\n" ::: "memory");
        __syncthreads();

        const uint32_t sa = tiles + (uint32_t)(c % FB_NSTAGE) * FB_STAGE;
        const uint32_t sb = sa + 16384u;

        #pragma unroll
        for (int kc = 0; kc < 4; kc++) {
            uint32_t a[4][4];
            uint32_t b[8][2];
            #pragma unroll
            for (int mt = 0; mt < 4; mt++) {
                int row = wm * 64 + mt * 16 + (lane & 15);
                uint32_t addr = sa + (uint32_t)row * 128 +
                    ((uint32_t)(((kc * 2 + (lane >> 4)) ^ (row & 7))) << 4);
                asm volatile(
                    "ldmatrix.sync.aligned.m8n8.x4.shared.b16 {%0,%1,%2,%3}, [%4];\n"
                    : "=r"(a[mt][0]), "=r"(a[mt][1]), "=r"(a[mt][2]), "=r"(a[mt][3])
                    : "r"(addr));
            }
            #pragma unroll
            for (int g = 0; g < 4; g++) {
                int row = wn * 64 + g * 16 + (lane & 15);
                uint32_t addr = sb + (uint32_t)row * 128 +
                    ((uint32_t)(((kc * 2 + (lane >> 4)) ^ (row & 7))) << 4);
                uint32_t q0, q1, q2, q3;
                asm volatile(
                    "ldmatrix.sync.aligned.m8n8.x4.shared.b16 {%0,%1,%2,%3}, [%4];\n"
                    : "=r"(q0), "=r"(q1), "=r"(q2), "=r"(q3)
                    : "r"(addr));
                b[g * 2 + 0][0] = q0; b[g * 2 + 0][1] = q2;
                b[g * 2 + 1][0] = q1; b[g * 2 + 1][1] = q3;
            }
            #pragma unroll
            for (int mt = 0; mt < 4; mt++) {
                #pragma unroll
                for (int nt = 0; nt < 8; nt++) {
                    asm volatile(
                        "mma.sync.aligned.m16n8k16.row.col.f32.f16.f16.f32 "
                        "{%0,%1,%2,%3}, {%4,%5,%6,%7}, {%8,%9}, {%0,%1,%2,%3};\n"
                        : "+f"(acc[mt][nt][0]), "+f"(acc[mt][nt][1]),
                          "+f"(acc[mt][nt][2]), "+f"(acc[mt][nt][3])
                        : "r"(a[mt][0]), "r"(a[mt][1]), "r"(a[mt][2]), "r"(a[mt][3]),
                          "r"(b[nt][0]), "r"(b[nt][1]));
                }
            }
        }
        __syncthreads();
        if (c + 3 < 64) fillf(c + 3);
        asm volatile("cp.async.commit_group;\n" ::: "memory");
    }

    #pragma unroll
    for (int mt = 0; mt < 4; mt++) {
        int row = m0 + wm * 64 + mt * 16 + (lane >> 2);
        #pragma unroll
        for (int nt = 0; nt < 8; nt++) {
            int col = n0 + wn * 64 + nt * 8 + (lane & 3) * 2;
            float b0 = bias[col];
            float b1 = bias[col + 1];
            float2 v0 = make_float2(acc[mt][nt][0] + b0, acc[mt][nt][1] + b1);
            float2 v1 = make_float2(acc[mt][nt][2] + b0, acc[mt][nt][3] + b1);
            *reinterpret_cast<float2*>(out + (size_t)row * OUT_F + col)       = v0;
            *reinterpret_cast<float2*>(out + (size_t)(row + 8) * OUT_F + col) = v1;
        }
    }
#endif
}

// ---------------------------------------------------------------------------
extern "C" void kernel_launch(void* const* d_in, const int* in_sizes, int n_in,
                              void* d_out, int out_size) {
    const float* x    = (const float*)d_in[0];
    const int*   q    = (const int*)  d_in[1];
    const float* sc   = (const float*)d_in[2];
    const float* bias = (const float*)d_in[3];
    const float* A    = (const float*)d_in[4];
    const float* B    = (const float*)d_in[5];
    float*       out  = (float*)d_out;

    (void)in_sizes; (void)n_in; (void)out_size;

    cudaFuncSetAttribute(k_gemm, cudaFuncAttributeMaxDynamicSharedMemorySize,
                         SMEM_DYN);

    k_sample_shift<<<1, 32>>>();
    k_convert_x<<<(MTOT * (size_t)IN_F) / (256 * 8), 256>>>(x);
    k_build_w<<<dim3(IN_F / 512, OUT_F / 128), 256>>>(q, sc, A, B);
    k_gemm<<<dim3(OUT_F / 256, MTOT / 128), 256, SMEM_DYN>>>(bias, out);
}

// round 12
// speedup vs baseline: 1.3583x; 1.3583x over previous
#include <cuda_runtime.h>
#include <cuda_fp16.h>
#include <cstdint>

#define IN_F   4096
#define OUT_F  4096
#define MTOT   8192
#define RANK   16
#define QBLOCK 64
#define SCALING 2.0f

// Two device passes: compute_103 (PTX, no tcgen05, compile-only fallback) and
// sm_103a (SASS, tcgen05 — this is the cubin that executes).
#if defined(__CUDA_ARCH_FEAT_SM103_ALL) || defined(__CUDA_ARCH_FEAT_SM100_ALL)
#define HAS_TCGEN05 1
#else
#define HAS_TCGEN05 0
#endif

// Scratch (allocation-free rule: __device__ globals)
__device__ __half g_X[(size_t)MTOT * IN_F];    // 64 MB fp16 activations
__device__ __half g_W[(size_t)OUT_F * IN_F];   // 32 MB fp16 effective weight

// ---------------------------------------------------------------------------
// Kernel 0: no-op — keeps ncu's sampled launch on the GEMM.
// ---------------------------------------------------------------------------
__global__ void k_sample_shift() {}

// ---------------------------------------------------------------------------
// Kernel 1 (fused prologue, proven r6/r7):
//   blocks [0,256)  -> build W_eff = dequant + SCALING*B@A   (FMA-bound)
//   blocks [256,..) -> convert x fp32->fp16                  (DRAM-bound)
// Overlapping the two hides the build behind the 28us HBM-bound convert.
// ---------------------------------------------------------------------------
__global__ void __launch_bounds__(256) k_prologue(const float* __restrict__ x,
                                                  const int*   __restrict__ q,
                                                  const float* __restrict__ sc,
                                                  const float* __restrict__ A,
                                                  const float* __restrict__ B) {
    const int t = threadIdx.x;

    if (blockIdx.x >= 256) {
        size_t idx  = (size_t)(blockIdx.x - 256) * 256 + t;
        size_t base = idx * 8;
        const float4* xv = reinterpret_cast<const float4*>(x + base);
        float4 a = xv[0];
        float4 b = xv[1];
        __half2 h0 = __floats2half2_rn(a.x, a.y);
        __half2 h1 = __floats2half2_rn(a.z, a.w);
        __half2 h2 = __floats2half2_rn(b.x, b.y);
        __half2 h3 = __floats2half2_rn(b.z, b.w);
        uint4 o;
        o.x = *reinterpret_cast<unsigned*>(&h0);
        o.y = *reinterpret_cast<unsigned*>(&h1);
        o.z = *reinterpret_cast<unsigned*>(&h2);
        o.w = *reinterpret_cast<unsigned*>(&h3);
        reinterpret_cast<uint4*>(g_X)[idx] = o;
        return;
    }

    __shared__ __align__(16) float Ash[RANK][512];   // 32 KB
    __shared__ __align__(16) float Bsh[128][16];     // 8 KB
    __shared__ float Ssh[128][8];                    // 4 KB

    const int i0 = (blockIdx.x & 7) * 512;
    const int o0 = (blockIdx.x >> 3) * 128;

    #pragma unroll
    for (int j = 0; j < 8; j++) {
        int idx = t + 256 * j;
        int r   = idx >> 7;
        int c4  = idx & 127;
        float4 v = reinterpret_cast<const float4*>(A + (size_t)r * IN_F + i0)[c4];
        *reinterpret_cast<float4*>(&Ash[r][c4 * 4]) = v;
    }
    #pragma unroll
    for (int j = 0; j < 8; j++) {
        int idx = t + 256 * j;
        int o   = idx >> 4;
        int r   = idx & 15;
        Bsh[o][r] = B[(size_t)(o0 + o) * RANK + r] * SCALING;
    }
    if (t < 128) {
        #pragma unroll
        for (int blk = 0; blk < 8; blk++)
            Ssh[t][blk] = sc[(size_t)(o0 + t) * (IN_F / QBLOCK) + (i0 >> 6) + blk];
    }
    __syncthreads();

    const int lane = t & 31;
    const int wid  = t >> 5;

    #pragma unroll
    for (int j = 0; j < 4; j++) {
        const int il = (j * 32 + lane) * 4;
        float4 a[RANK];
        #pragma unroll
        for (int r = 0; r < RANK; r++)
            a[r] = *reinterpret_cast<const float4*>(&Ash[r][il]);

        #pragma unroll 2
        for (int oo = 0; oo < 16; oo++) {
            const int    ol   = (wid << 4) + oo;
            const int    o    = o0 + ol;
            const size_t orow = (size_t)o * IN_F;
            const int4   q4   = *reinterpret_cast<const int4*>(q + orow + i0 + il);
            const float  s    = Ssh[ol][il >> 6];

            float4 acc;
            acc.x = (float)(q4.x - 8) * s;
            acc.y = (float)(q4.y - 8) * s;
            acc.z = (float)(q4.z - 8) * s;
            acc.w = (float)(q4.w - 8) * s;

            const float4 b0 = *reinterpret_cast<const float4*>(&Bsh[ol][0]);
            const float4 b1 = *reinterpret_cast<const float4*>(&Bsh[ol][4]);
            const float4 b2 = *reinterpret_cast<const float4*>(&Bsh[ol][8]);
            const float4 b3 = *reinterpret_cast<const float4*>(&Bsh[ol][12]);
            const float bb[16] = { b0.x,b0.y,b0.z,b0.w, b1.x,b1.y,b1.z,b1.w,
                                   b2.x,b2.y,b2.z,b2.w, b3.x,b3.y,b3.z,b3.w };
            #pragma unroll
            for (int r = 0; r < RANK; r++) {
                acc.x += bb[r] * a[r].x;
                acc.y += bb[r] * a[r].y;
                acc.z += bb[r] * a[r].z;
                acc.w += bb[r] * a[r].w;
            }
            __half2 h0 = __floats2half2_rn(acc.x, acc.y);
            __half2 h1 = __floats2half2_rn(acc.z, acc.w);
            uint2 st;
            st.x = *reinterpret_cast<unsigned*>(&h0);
            st.y = *reinterpret_cast<unsigned*>(&h1);
            *reinterpret_cast<uint2*>(g_W + orow + i0 + il) = st;
        }
    }
}

// ---------------------------------------------------------------------------
// Kernel 2: GEMM — EXACT round-9 body (proven 223.7us, tensor 53.7%).
// CTA tile 128x256, 4-stage ring (48KB/stage), fill-ahead 2 -> two MMA chunks
// in flight.  Lockstep (one __syncthreads per chunk) — the warp-specialized
// variants (r10/r11) regressed or broke; this is the trusted schedule.
// ---------------------------------------------------------------------------
#define TC_NSTAGE   4
#define TC_STAGE    49152u             // 128 A rows + 256 B rows, 128B each
#define FB_NSTAGE   3
#define FB_STAGE    49152u
#define SMEM_DYN    (2048 + 4 * 49152)
#define IDESC       0x8400010u         // F32 D, F16 A/B, N=256, M=128

// SW128 K-major smem descriptor base (layout=2, ver=1, SBO=64, LBO=1)
#define DESC_BASE ( (2ull << 61) | (1ull << 46) | (64ull << 32) | (1ull << 16) )
#define MAKE_DESC(addr) (DESC_BASE | ((uint64_t)((addr) >> 4) & 0x3FFF))

__device__ __forceinline__ uint32_t smem_u32(const void* p) {
    uint32_t a;
    asm("{ .reg .u64 t; cvta.to.shared.u64 t, %1; cvt.u32.u64 %0, t; }"
        : "=r"(a) : "l"(p));
    return a;
}

__device__ __forceinline__ void cp16(uint32_t smem, const void* gmem) {
    asm volatile("cp.async.cg.shared.global [%0], [%1], 16;\n"
                 :: "r"(smem), "l"(gmem) : "memory");
}

#if HAS_TCGEN05
__device__ __forceinline__ uint32_t elect_one() {
    uint32_t p;
    asm volatile("{ .reg .pred p; elect.sync _|p, 0xFFFFFFFF; selp.b32 %0, 1, 0, p; }"
                 : "=r"(p));
    return p;
}
__device__ __forceinline__ void mma_f16_ss(uint32_t d, uint64_t ad, uint64_t bd,
                                           uint32_t en) {
    asm volatile(
        "{\n\t"
        ".reg .pred p;\n\t"
        "setp.ne.u32 p, %4, 0;\n\t"
        "tcgen05.mma.cta_group::1.kind::f16 [%0], %1, %2, %3, {%5,%5,%5,%5}, p;\n\t"
        "}"
        :: "r"(d), "l"(ad), "l"(bd), "r"(IDESC), "r"(en), "r"(0u) : "memory");
}
__device__ __forceinline__ void mbar_init(uint32_t mb, uint32_t cnt) {
    asm volatile("mbarrier.init.shared.b64 [%0], %1;" :: "r"(mb), "r"(cnt) : "memory");
}
__device__ __forceinline__ void mbar_wait(uint32_t mb, uint32_t parity) {
    asm volatile(
        "{\n\t"
        ".reg .pred P;\n\t"
        "LAB_WAIT_%=:\n\t"
        "mbarrier.try_wait.parity.acquire.cta.shared::cta.b64 P, [%0], %1, 0x989680;\n\t"
        "@P bra.uni LAB_DONE_%=;\n\t"
        "bra.uni LAB_WAIT_%=;\n\t"
        "LAB_DONE_%=:\n\t"
        "}"
        :: "r"(mb), "r"(parity) : "memory");
}
#endif

__global__ void __launch_bounds__(256, 1) k_gemm(const float* __restrict__ bias,
                                                 float* __restrict__ out) {
    extern __shared__ char smem[];
    const uint32_t smem_base = smem_u32(smem);
    const uint32_t tiles = (smem_base + 48 + 1023) & ~1023u;

    const int t    = threadIdx.x;
    const int lane = t & 31;
    const int wid  = t >> 5;

    const int r0   = t >> 3;                                    // 0..31
    const int csrc = (t & 7) * 8;                               // K halves
    const uint32_t chs = (uint32_t)(((t & 7) ^ (r0 & 7)) << 4); // SW128 16B chunk

#if HAS_TCGEN05
    // ======================= tcgen05 path (EXECUTES) =======================
    const int m0 = blockIdx.y * 128;
    const int n0 = blockIdx.x * 256;

    if (wid == 0) {
        asm volatile("tcgen05.alloc.cta_group::1.sync.aligned.shared::cta.b32 [%0], %1;"
                     :: "r"(smem_base), "r"(256u) : "memory");
        asm volatile("tcgen05.relinquish_alloc_permit.cta_group::1.sync.aligned;");
    }
    if (t == 0) {
        mbar_init(smem_base + 8,  1);
        mbar_init(smem_base + 16, 1);
        mbar_init(smem_base + 24, 1);
        mbar_init(smem_base + 32, 1);
    }
    __syncthreads();
    uint32_t tmem;
    asm volatile("ld.shared.b32 %0, [%1];" : "=r"(tmem) : "r"(smem_base));

    const __half* gA = g_X + (size_t)m0 * IN_F;
    const __half* gB = g_W + (size_t)n0 * IN_F;

    auto fill = [&](int f) {
        const uint32_t sb   = tiles + (uint32_t)(f & (TC_NSTAGE - 1)) * TC_STAGE;
        const int      koff = f * 64;
        #pragma unroll
        for (int j = 0; j < 4; j++) {                 // A: 128 rows
            int row = r0 + 32 * j;
            cp16(sb + (uint32_t)row * 128 + chs,
                 gA + (size_t)row * IN_F + koff + csrc);
        }
        #pragma unroll
        for (int j = 0; j < 8; j++) {                 // B: 256 rows
            int row = r0 + 32 * j;
            cp16(sb + 16384u + (uint32_t)row * 128 + chs,
                 gB + (size_t)row * IN_F + koff + csrc);
        }
    };

    const int KT = IN_F / 64;   // 64 chunks
    int ph = 0;

    // fill-ahead 2: stages 0,1 in flight
    fill(0);
    asm volatile("cp.async.commit_group;\n" ::: "memory");
    fill(1);
    asm volatile("cp.async.commit_group;\n" ::: "memory");

    for (int c = 0; c < KT; c++) {
        const int fs = c + 2;
        if (fs < KT) {
            if (c >= 2) {
                // buffer (c+2)&3 was last read by MMA chunk c-2 -> depth-2 queue
                const int slot = fs & 3;
                mbar_wait(smem_base + 8 + slot * 8, (ph >> slot) & 1);
                ph ^= (1 << slot);
            }
            fill(fs);
        }
        asm volatile("cp.async.commit_group;\n" ::: "memory");
        asm volatile("cp.async.wait_group 2;\n" ::: "memory");
        __syncthreads();

        if (wid == 0) {
            asm volatile("fence.proxy.async.shared::cta;" ::: "memory");
            if (elect_one()) {
                const uint32_t sb = tiles + (uint32_t)(c & (TC_NSTAGE - 1)) * TC_STAGE;
                const uint64_t ad = MAKE_DESC(sb);
                const uint64_t bd = MAKE_DESC(sb + 16384u);
                #pragma unroll
                for (int j = 0; j < 4; j++)
                    mma_f16_ss(tmem, ad + j * 2, bd + j * 2,
                               (c > 0 || j > 0) ? 1u : 0u);
                asm volatile(
                    "tcgen05.commit.cta_group::1.mbarrier::arrive::one.shared::cluster.b64 [%0];"
                    :: "r"(smem_base + 8 + (c & (TC_NSTAGE - 1)) * 8) : "memory");
            }
        }
    }
    {
        const int slot = (KT - 1) & (TC_NSTAGE - 1);
        mbar_wait(smem_base + 8 + slot * 8, (ph >> slot) & 1);
    }
    asm volatile("tcgen05.fence::after_thread_sync;" ::: "memory");

    // Epilogue: 8 warps = (subpartition wid&3) x (col-half wid>>2)
    {
        const int subp  = wid & 3;
        const int chalf = wid >> 2;
        const int m     = m0 + subp * 32 + lane;
        const int cbase = chalf * 128;
        float* orow     = out + (size_t)m * OUT_F + n0 + cbase;
        const uint32_t dbase = tmem + cbase;

        #pragma unroll
        for (int cc = 0; cc < 4; cc++) {
            uint32_t r[32];
            asm volatile(
                "tcgen05.ld.sync.aligned.32x32b.x32.b32 "
                "{%0,%1,%2,%3,%4,%5,%6,%7,%8,%9,%10,%11,%12,%13,%14,%15,"
                "%16,%17,%18,%19,%20,%21,%22,%23,%24,%25,%26,%27,%28,%29,%30,%31}, [%32];"
                : "=r"(r[0]),  "=r"(r[1]),  "=r"(r[2]),  "=r"(r[3]),
                  "=r"(r[4]),  "=r"(r[5]),  "=r"(r[6]),  "=r"(r[7]),
                  "=r"(r[8]),  "=r"(r[9]),  "=r"(r[10]), "=r"(r[11]),
                  "=r"(r[12]), "=r"(r[13]), "=r"(r[14]), "=r"(r[15]),
                  "=r"(r[16]), "=r"(r[17]), "=r"(r[18]), "=r"(r[19]),
                  "=r"(r[20]), "=r"(r[21]), "=r"(r[22]), "=r"(r[23]),
                  "=r"(r[24]), "=r"(r[25]), "=r"(r[26]), "=r"(r[27]),
                  "=r"(r[28]), "=r"(r[29]), "=r"(r[30]), "=r"(r[31])
                : "r"(dbase + cc * 32));
            asm volatile("tcgen05.wait::ld.sync.aligned;" ::: "memory");

            const float4* bv = reinterpret_cast<const float4*>(bias + n0 + cbase + cc * 32);
            float4* ov = reinterpret_cast<float4*>(orow + cc * 32);
            #pragma unroll
            for (int v = 0; v < 8; v++) {
                float4 b4 = bv[v];
                float4 o4;
                o4.x = __uint_as_float(r[4 * v + 0]) + b4.x;
                o4.y = __uint_as_float(r[4 * v + 1]) + b4.y;
                o4.z = __uint_as_float(r[4 * v + 2]) + b4.z;
                o4.w = __uint_as_float(r[4 * v + 3]) + b4.w;
                ov[v] = o4;
            }
        }
    }
    __syncthreads();
    if (wid == 0) {
        asm volatile("tcgen05.dealloc.cta_group::1.sync.aligned.b32 %0, %1;"
                     :: "r"(tmem), "r"(256u));
    }
#else
    // ============== HMMA fallback (compile-only on compute_103) ==========
    const int m0 = blockIdx.y * 128;
    const int n0 = blockIdx.x * 256;
    const int wm = wid & 1;
    const int wn = wid >> 1;

    const __half* gA = g_X + (size_t)m0 * IN_F;
    const __half* gB = g_W + (size_t)n0 * IN_F;

    auto fillf = [&](int f) {
        const uint32_t sb   = tiles + (uint32_t)(f % FB_NSTAGE) * FB_STAGE;
        const int      koff = f * 64;
        #pragma unroll
        for (int j = 0; j < 4; j++) {
            int row = r0 + 32 * j;
            cp16(sb + (uint32_t)row * 128 + chs,
                 gA + (size_t)row * IN_F + koff + csrc);
        }
        #pragma unroll
        for (int j = 0; j < 8; j++) {
            int row = r0 + 32 * j;
            cp16(sb + 16384u + (uint32_t)row * 128 + chs,
                 gB + (size_t)row * IN_F + koff + csrc);
        }
    };

    float acc[4][8][4];
    #pragma unroll
    for (int i = 0; i < 4; i++)
        #pragma unroll
        for (int j = 0; j < 8; j++)
            #pragma unroll
            for (int k = 0; k < 4; k++) acc[i][j][k] = 0.f;

    fillf(0);
    asm volatile("cp.async.commit_group;\n" ::: "memory");
    fillf(1);
    asm volatile("cp.async.commit_group;\n" ::: "memory");
    fillf(2);
    asm volatile("cp.async.commit_group;\n" ::: "memory");

    for (int c = 0; c < 64; c++) {
        asm volatile("cp.async.wait_group 2;\n" ::: "memory");
        __syncthreads();

        const uint32_t sa = tiles + (uint32_t)(c % FB_NSTAGE) * FB_STAGE;
        const uint32_t sb = sa + 16384u;

        #pragma unroll
        for (int kc = 0; kc < 4; kc++) {
            uint32_t a[4][4];
            uint32_t b[8][2];
            #pragma unroll
            for (int mt = 0; mt < 4; mt++) {
                int row = wm * 64 + mt * 16 + (lane & 15);
                uint32_t addr = sa + (uint32_t)row * 128 +
                    ((uint32_t)(((kc * 2 + (lane >> 4)) ^ (row & 7))) << 4);
                asm volatile(
                    "ldmatrix.sync.aligned.m8n8.x4.shared.b16 {%0,%1,%2,%3}, [%4];\n"
                    : "=r"(a[mt][0]), "=r"(a[mt][1]), "=r"(a[mt][2]), "=r"(a[mt][3])
                    : "r"(addr));
            }
            #pragma unroll
            for (int g = 0; g < 4; g++) {
                int row = wn * 64 + g * 16 + (lane & 15);
                uint32_t addr = sb + (uint32_t)row * 128 +
                    ((uint32_t)(((kc * 2 + (lane >> 4)) ^ (row & 7))) << 4);
                uint32_t q0, q1, q2, q3;
                asm volatile(
                    "ldmatrix.sync.aligned.m8n8.x4.shared.b16 {%0,%1,%2,%3}, [%4];\n"
                    : "=r"(q0), "=r"(q1), "=r"(q2), "=r"(q3)
                    : "r"(addr));
                b[g * 2 + 0][0] = q0; b[g * 2 + 0][1] = q2;
                b[g * 2 + 1][0] = q1; b[g * 2 + 1][1] = q3;
            }
            #pragma unroll
            for (int mt = 0; mt < 4; mt++) {
                #pragma unroll
                for (int nt = 0; nt < 8; nt++) {
                    asm volatile(
                        "mma.sync.aligned.m16n8k16.row.col.f32.f16.f16.f32 "
                        "{%0,%1,%2,%3}, {%4,%5,%6,%7}, {%8,%9}, {%0,%1,%2,%3};\n"
                        : "+f"(acc[mt][nt][0]), "+f"(acc[mt][nt][1]),
                          "+f"(acc[mt][nt][2]), "+f"(acc[mt][nt][3])
                        : "r"(a[mt][0]), "r"(a[mt][1]), "r"(a[mt][2]), "r"(a[mt][3]),
                          "r"(b[nt][0]), "r"(b[nt][1]));
                }
            }
        }
        __syncthreads();
        if (c + 3 < 64) fillf(c + 3);
        asm volatile("cp.async.commit_group;\n" ::: "memory");
    }

    #pragma unroll
    for (int mt = 0; mt < 4; mt++) {
        int row = m0 + wm * 64 + mt * 16 + (lane >> 2);
        #pragma unroll
        for (int nt = 0; nt < 8; nt++) {
            int col = n0 + wn * 64 + nt * 8 + (lane & 3) * 2;
            float b0 = bias[col];
            float b1 = bias[col + 1];
            float2 v0 = make_float2(acc[mt][nt][0] + b0, acc[mt][nt][1] + b1);
            float2 v1 = make_float2(acc[mt][nt][2] + b0, acc[mt][nt][3] + b1);
            *reinterpret_cast<float2*>(out + (size_t)row * OUT_F + col)       = v0;
            *reinterpret_cast<float2*>(out + (size_t)(row + 8) * OUT_F + col) = v1;
        }
    }
#endif
}

// ---------------------------------------------------------------------------
extern "C" void kernel_launch(void* const* d_in, const int* in_sizes, int n_in,
                              void* d_out, int out_size) {
    const float* x    = (const float*)d_in[0];
    const int*   q    = (const int*)  d_in[1];
    const float* sc   = (const float*)d_in[2];
    const float* bias = (const float*)d_in[3];
    const float* A    = (const float*)d_in[4];
    const float* B    = (const float*)d_in[5];
    float*       out  = (float*)d_out;

    (void)in_sizes; (void)n_in; (void)out_size;

    cudaFuncSetAttribute(k_gemm, cudaFuncAttributeMaxDynamicSharedMemorySize,
                         SMEM_DYN);

    k_sample_shift<<<1, 32>>>();
    k_sample_shift<<<1, 32>>>();
    k_prologue<<<256 + (MTOT * (size_t)IN_F) / (256 * 8), 256>>>(x, q, sc, A, B);
    k_gemm<<<dim3(OUT_F / 256, MTOT / 128), 256, SMEM_DYN>>>(bias, out);
}

// round 13
// speedup vs baseline: 1.4388x; 1.0593x over previous
#include <cuda_runtime.h>
#include <cuda_fp16.h>
#include <cstdint>

#define IN_F   4096
#define OUT_F  4096
#define MTOT   8192
#define RANK   16
#define QBLOCK 64
#define SCALING 2.0f

// Two device passes: compute_103 (PTX, no tcgen05, compile-only fallback) and
// sm_103a (SASS, tcgen05 — this is the cubin that executes).
#if defined(__CUDA_ARCH_FEAT_SM103_ALL) || defined(__CUDA_ARCH_FEAT_SM100_ALL)
#define HAS_TCGEN05 1
#else
#define HAS_TCGEN05 0
#endif

// Scratch (allocation-free rule: __device__ globals)
__device__ __half g_X[(size_t)MTOT * IN_F];    // 64 MB fp16 activations
__device__ __half g_W[(size_t)OUT_F * IN_F];   // 32 MB fp16 effective weight

// ---------------------------------------------------------------------------
// Kernel 0: no-op — keeps ncu's sampled launch on the GEMM.
// ---------------------------------------------------------------------------
__global__ void k_sample_shift() {}

// ---------------------------------------------------------------------------
// Kernel 1: convert x (fp32 -> fp16)  — 28us, HBM-bound.  (Separate kernels
// beat the fused prologue by ~17us — measured r9 vs r12.)
// ---------------------------------------------------------------------------
__global__ void k_convert_x(const float* __restrict__ x) {
    size_t idx  = (size_t)blockIdx.x * blockDim.x + threadIdx.x;
    size_t base = idx * 8;
    const float4* xv = reinterpret_cast<const float4*>(x + base);
    float4 a = xv[0];
    float4 b = xv[1];
    __half2 h0 = __floats2half2_rn(a.x, a.y);
    __half2 h1 = __floats2half2_rn(a.z, a.w);
    __half2 h2 = __floats2half2_rn(b.x, b.y);
    __half2 h3 = __floats2half2_rn(b.z, b.w);
    uint4 o;
    o.x = *reinterpret_cast<unsigned*>(&h0);
    o.y = *reinterpret_cast<unsigned*>(&h1);
    o.z = *reinterpret_cast<unsigned*>(&h2);
    o.w = *reinterpret_cast<unsigned*>(&h3);
    reinterpret_cast<uint4*>(g_X)[idx] = o;
}

// ---------------------------------------------------------------------------
// Kernel 2: W_eff = dequant(q,scales) + SCALING * B@A  (fp16 out)
// ---------------------------------------------------------------------------
__global__ void k_build_w(const int*   __restrict__ q,
                          const float* __restrict__ sc,
                          const float* __restrict__ A,
                          const float* __restrict__ B) {
    __shared__ __align__(16) float Ash[RANK][512];   // 32 KB
    __shared__ __align__(16) float Bsh[128][16];     // 8 KB
    __shared__ float Ssh[128][8];                    // 4 KB

    const int t  = threadIdx.x;            // 256 threads
    const int i0 = blockIdx.x * 512;
    const int o0 = blockIdx.y * 128;

    #pragma unroll
    for (int j = 0; j < 8; j++) {
        int idx = t + 256 * j;
        int r   = idx >> 7;
        int c4  = idx & 127;
        float4 v = reinterpret_cast<const float4*>(A + (size_t)r * IN_F + i0)[c4];
        *reinterpret_cast<float4*>(&Ash[r][c4 * 4]) = v;
    }
    #pragma unroll
    for (int j = 0; j < 8; j++) {
        int idx = t + 256 * j;
        int o   = idx >> 4;
        int r   = idx & 15;
        Bsh[o][r] = B[(size_t)(o0 + o) * RANK + r] * SCALING;
    }
    if (t < 128) {
        #pragma unroll
        for (int blk = 0; blk < 8; blk++)
            Ssh[t][blk] = sc[(size_t)(o0 + t) * (IN_F / QBLOCK) + (i0 >> 6) + blk];
    }
    __syncthreads();

    const int lane = t & 31;
    const int wid  = t >> 5;

    #pragma unroll
    for (int j = 0; j < 4; j++) {
        const int il = (j * 32 + lane) * 4;
        float4 a[RANK];
        #pragma unroll
        for (int r = 0; r < RANK; r++)
            a[r] = *reinterpret_cast<const float4*>(&Ash[r][il]);

        #pragma unroll 2
        for (int oo = 0; oo < 16; oo++) {
            const int    ol   = (wid << 4) + oo;
            const int    o    = o0 + ol;
            const size_t orow = (size_t)o * IN_F;
            const int4   q4   = *reinterpret_cast<const int4*>(q + orow + i0 + il);
            const float  s    = Ssh[ol][il >> 6];

            float4 acc;
            acc.x = (float)(q4.x - 8) * s;
            acc.y = (float)(q4.y - 8) * s;
            acc.z = (float)(q4.z - 8) * s;
            acc.w = (float)(q4.w - 8) * s;

            const float4 b0 = *reinterpret_cast<const float4*>(&Bsh[ol][0]);
            const float4 b1 = *reinterpret_cast<const float4*>(&Bsh[ol][4]);
            const float4 b2 = *reinterpret_cast<const float4*>(&Bsh[ol][8]);
            const float4 b3 = *reinterpret_cast<const float4*>(&Bsh[ol][12]);
            const float bb[16] = { b0.x,b0.y,b0.z,b0.w, b1.x,b1.y,b1.z,b1.w,
                                   b2.x,b2.y,b2.z,b2.w, b3.x,b3.y,b3.z,b3.w };
            #pragma unroll
            for (int r = 0; r < RANK; r++) {
                acc.x += bb[r] * a[r].x;
                acc.y += bb[r] * a[r].y;
                acc.z += bb[r] * a[r].z;
                acc.w += bb[r] * a[r].w;
            }
            __half2 h0 = __floats2half2_rn(acc.x, acc.y);
            __half2 h1 = __floats2half2_rn(acc.z, acc.w);
            uint2 st;
            st.x = *reinterpret_cast<unsigned*>(&h0);
            st.y = *reinterpret_cast<unsigned*>(&h1);
            *reinterpret_cast<uint2*>(g_W + orow + i0 + il) = st;
        }
    }
}

// ---------------------------------------------------------------------------
// Kernel 3: GEMM out = Xh @ W^T + bias.  grid (16,32), 256 thr.
//   tcgen05 (EXECUTES): CTA tile 256x256 (traffic 2.0GB vs 3.1GB at 128x256 —
//     the 128x256 version measured AT the LTS cap, 13.8TB/s).  3 stages of
//     64KB.  Loop REORDERED vs r8: MMA(c) issues FIRST (data awaited last
//     iter), THEN wait commit(c-1) for slot reuse + fill(c+2).  This takes the
//     MMA-completion wait off the MMA-issue path that made r8 depth-1.
//   HMMA fallback (#else): compile-only for the compute_103 PTX pass.
// ---------------------------------------------------------------------------
#define TC_NSTAGE   3
#define TC_STAGE    65536u             // 256 A rows + 256 B rows, 128B each
#define FB_NSTAGE   3
#define FB_STAGE    49152u
#define SMEM_DYN    (2048 + 3 * 65536)
#define IDESC       0x8400010u         // F32 D, F16 A/B, N=256, M=128

// SW128 K-major smem descriptor base (layout=2, ver=1, SBO=64, LBO=1)
#define DESC_BASE ( (2ull << 61) | (1ull << 46) | (64ull << 32) | (1ull << 16) )
#define MAKE_DESC(addr) (DESC_BASE | ((uint64_t)((addr) >> 4) & 0x3FFF))

__device__ __forceinline__ uint32_t smem_u32(const void* p) {
    uint32_t a;
    asm("{ .reg .u64 t; cvta.to.shared.u64 t, %1; cvt.u32.u64 %0, t; }"
        : "=r"(a) : "l"(p));
    return a;
}

__device__ __forceinline__ void cp16(uint32_t smem, const void* gmem) {
    asm volatile("cp.async.cg.shared.global [%0], [%1], 16;\n"
                 :: "r"(smem), "l"(gmem) : "memory");
}

#if HAS_TCGEN05
__device__ __forceinline__ uint32_t elect_one() {
    uint32_t p;
    asm volatile("{ .reg .pred p; elect.sync _|p, 0xFFFFFFFF; selp.b32 %0, 1, 0, p; }"
                 : "=r"(p));
    return p;
}
__device__ __forceinline__ void mma_f16_ss(uint32_t d, uint64_t ad, uint64_t bd,
                                           uint32_t en) {
    asm volatile(
        "{\n\t"
        ".reg .pred p;\n\t"
        "setp.ne.u32 p, %4, 0;\n\t"
        "tcgen05.mma.cta_group::1.kind::f16 [%0], %1, %2, %3, {%5,%5,%5,%5}, p;\n\t"
        "}"
        :: "r"(d), "l"(ad), "l"(bd), "r"(IDESC), "r"(en), "r"(0u) : "memory");
}
__device__ __forceinline__ void mbar_init(uint32_t mb, uint32_t cnt) {
    asm volatile("mbarrier.init.shared.b64 [%0], %1;" :: "r"(mb), "r"(cnt) : "memory");
}
__device__ __forceinline__ void mbar_wait(uint32_t mb, uint32_t parity) {
    asm volatile(
        "{\n\t"
        ".reg .pred P;\n\t"
        "LAB_WAIT_%=:\n\t"
        "mbarrier.try_wait.parity.acquire.cta.shared::cta.b64 P, [%0], %1, 0x989680;\n\t"
        "@P bra.uni LAB_DONE_%=;\n\t"
        "bra.uni LAB_WAIT_%=;\n\t"
        "LAB_DONE_%=:\n\t"
        "}"
        :: "r"(mb), "r"(parity) : "memory");
}
#endif

__global__ void __launch_bounds__(256, 1) k_gemm(const float* __restrict__ bias,
                                                 float* __restrict__ out) {
    extern __shared__ char smem[];
    const uint32_t smem_base = smem_u32(smem);
    const uint32_t tiles = (smem_base + 48 + 1023) & ~1023u;

    const int t    = threadIdx.x;
    const int lane = t & 31;
    const int wid  = t >> 5;

    const int r0   = t >> 3;                                    // 0..31
    const int csrc = (t & 7) * 8;                               // K halves
    const uint32_t chs = (uint32_t)(((t & 7) ^ (r0 & 7)) << 4); // SW128 16B chunk

#if HAS_TCGEN05
    // ======================= tcgen05 path (EXECUTES) =======================
    const int m0 = blockIdx.y * 256;
    const int n0 = blockIdx.x * 256;

    if (wid == 0) {
        asm volatile("tcgen05.alloc.cta_group::1.sync.aligned.shared::cta.b32 [%0], %1;"
                     :: "r"(smem_base), "r"(512u) : "memory");
        asm volatile("tcgen05.relinquish_alloc_permit.cta_group::1.sync.aligned;");
    }
    if (t == 0) {
        mbar_init(smem_base + 8,  1);   // done[0]
        mbar_init(smem_base + 16, 1);   // done[1]
        mbar_init(smem_base + 24, 1);   // done[2]
    }
    __syncthreads();
    uint32_t tmem;
    asm volatile("ld.shared.b32 %0, [%1];" : "=r"(tmem) : "r"(smem_base));

    const __half* gA = g_X + (size_t)m0 * IN_F;
    const __half* gB = g_W + (size_t)n0 * IN_F;

    auto fill = [&](int f) {
        const uint32_t sb   = tiles + (uint32_t)(f % TC_NSTAGE) * TC_STAGE;
        const int      koff = f * 64;
        #pragma unroll
        for (int j = 0; j < 8; j++) {
            int row = r0 + 32 * j;
            cp16(sb + (uint32_t)row * 128 + chs,
                 gA + (size_t)row * IN_F + koff + csrc);
            cp16(sb + 32768u + (uint32_t)row * 128 + chs,
                 gB + (size_t)row * IN_F + koff + csrc);
        }
    };

    const int KT = IN_F / 64;   // 64 chunks

    // Prologue: fill stages 0,1; ensure fill(0) complete.
    fill(0);
    asm volatile("cp.async.commit_group;\n" ::: "memory");
    fill(1);
    asm volatile("cp.async.commit_group;\n" ::: "memory");
    asm volatile("cp.async.wait_group 1;\n" ::: "memory");
    __syncthreads();

    for (int c = 0; c < KT; c++) {
        // 1) MMA(c) FIRST — its stage was completed and synced last iteration.
        if (wid == 0) {
            asm volatile("fence.proxy.async.shared::cta;" ::: "memory");
            if (elect_one()) {
                const uint32_t sb = tiles + (uint32_t)(c % TC_NSTAGE) * TC_STAGE;
                const uint64_t ad = MAKE_DESC(sb);
                const uint64_t bd = MAKE_DESC(sb + 32768u);
                #pragma unroll
                for (int s = 0; s < 2; s++) {
                    const uint32_t d   = tmem + s * 256;
                    const uint64_t ads = ad + (uint64_t)s * 1024;
                    #pragma unroll
                    for (int j = 0; j < 4; j++)
                        mma_f16_ss(d, ads + j * 2, bd + j * 2,
                                   (c > 0 || j > 0) ? 1u : 0u);
                }
                asm volatile(
                    "tcgen05.commit.cta_group::1.mbarrier::arrive::one.shared::cluster.b64 [%0];"
                    :: "r"(smem_base + 8 + (c % TC_NSTAGE) * 8) : "memory");
            }
        }

        // 2) Refill stage for chunk c+2 (slot == (c-1)%3, last read by MMA c-1).
        const int fs = c + 2;
        if (fs < KT) {
            if (c >= 1) {
                const int slot = fs % TC_NSTAGE;          // == (c-1)%3
                mbar_wait(smem_base + 8 + slot * 8, (uint32_t)(((c - 1) / 3) & 1));
            }
            fill(fs);
        }
        asm volatile("cp.async.commit_group;\n" ::: "memory");
        // 3) Ensure fill(c+1) landed so next iteration's MMA can go immediately.
        asm volatile("cp.async.wait_group 1;\n" ::: "memory");
        __syncthreads();
    }

    // Wait for final MMA chunk: done[(KT-1)%3], occurrence (KT-1)/3.
    mbar_wait(smem_base + 8 + ((KT - 1) % TC_NSTAGE) * 8,
              (uint32_t)(((KT - 1) / 3) & 1));
    asm volatile("tcgen05.fence::after_thread_sync;" ::: "memory");

    // Epilogue (r8-proven): slice = wid>>2 picks TMEM col half, wid&3 = subp.
    {
        const int slice = wid >> 2;
        const int w4    = wid & 3;
        const int m     = m0 + slice * 128 + w4 * 32 + lane;
        float* orow     = out + (size_t)m * OUT_F + n0;
        const uint32_t dbase = tmem + slice * 256;
        #pragma unroll
        for (int cc = 0; cc < 8; cc++) {
            uint32_t r[32];
            asm volatile(
                "tcgen05.ld.sync.aligned.32x32b.x32.b32 "
                "{%0,%1,%2,%3,%4,%5,%6,%7,%8,%9,%10,%11,%12,%13,%14,%15,"
                "%16,%17,%18,%19,%20,%21,%22,%23,%24,%25,%26,%27,%28,%29,%30,%31}, [%32];"
                : "=r"(r[0]),  "=r"(r[1]),  "=r"(r[2]),  "=r"(r[3]),
                  "=r"(r[4]),  "=r"(r[5]),  "=r"(r[6]),  "=r"(r[7]),
                  "=r"(r[8]),  "=r"(r[9]),  "=r"(r[10]), "=r"(r[11]),
                  "=r"(r[12]), "=r"(r[13]), "=r"(r[14]), "=r"(r[15]),
                  "=r"(r[16]), "=r"(r[17]), "=r"(r[18]), "=r"(r[19]),
                  "=r"(r[20]), "=r"(r[21]), "=r"(r[22]), "=r"(r[23]),
                  "=r"(r[24]), "=r"(r[25]), "=r"(r[26]), "=r"(r[27]),
                  "=r"(r[28]), "=r"(r[29]), "=r"(r[30]), "=r"(r[31])
                : "r"(dbase + cc * 32));
            asm volatile("tcgen05.wait::ld.sync.aligned;" ::: "memory");

            const float4* bv = reinterpret_cast<const float4*>(bias + n0 + cc * 32);
            float4* ov = reinterpret_cast<float4*>(orow + cc * 32);
            #pragma unroll
            for (int v = 0; v < 8; v++) {
                float4 b4 = bv[v];
                float4 o4;
                o4.x = __uint_as_float(r[4 * v + 0]) + b4.x;
                o4.y = __uint_as_float(r[4 * v + 1]) + b4.y;
                o4.z = __uint_as_float(r[4 * v + 2]) + b4.z;
                o4.w = __uint_as_float(r[4 * v + 3]) + b4.w;
                ov[v] = o4;
            }
        }
    }
    __syncthreads();
    if (wid == 0) {
        asm volatile("tcgen05.dealloc.cta_group::1.sync.aligned.b32 %0, %1;"
                     :: "r"(tmem), "r"(512u));
    }
#else
    // ============== HMMA fallback (compile-only on compute_103) ==========
    // 256x256 CTA tile as two 128x256 halves; 8 warps 2(m)x4(n), warp 64x64.
    const int wm = wid & 1;
    const int wn = wid >> 1;

    for (int mh = 0; mh < 2; mh++) {
        const __half* gA = g_X + (size_t)(blockIdx.y * 256 + mh * 128) * IN_F;
        const __half* gB = g_W + (size_t)(blockIdx.x * 256) * IN_F;

        auto fillf = [&](int f) {
            const uint32_t sb   = tiles + (uint32_t)(f % FB_NSTAGE) * FB_STAGE;
            const int      koff = f * 64;
            #pragma unroll
            for (int j = 0; j < 4; j++) {
                int row = r0 + 32 * j;
                cp16(sb + (uint32_t)row * 128 + chs,
                     gA + (size_t)row * IN_F + koff + csrc);
            }
            #pragma unroll
            for (int j = 0; j < 8; j++) {
                int row = r0 + 32 * j;
                cp16(sb + 16384u + (uint32_t)row * 128 + chs,
                     gB + (size_t)row * IN_F + koff + csrc);
            }
        };

        float acc[4][8][4];
        #pragma unroll
        for (int i = 0; i < 4; i++)
            #pragma unroll
            for (int j = 0; j < 8; j++)
                #pragma unroll
                for (int k = 0; k < 4; k++) acc[i][j][k] = 0.f;

        fillf(0);
        asm volatile("cp.async.commit_group;\n" ::: "memory");
        fillf(1);
        asm volatile("cp.async.commit_group;\n" ::: "memory");
        fillf(2);
        asm volatile("cp.async.commit_group;\n" ::: "memory");

        for (int c = 0; c < 64; c++) {
            asm volatile("cp.async.wait_group 2;\n" ::: "memory");
            __syncthreads();

            const uint32_t sa = tiles + (uint32_t)(c % FB_NSTAGE) * FB_STAGE;
            const uint32_t sb = sa + 16384u;

            #pragma unroll
            for (int kc = 0; kc < 4; kc++) {
                uint32_t a[4][4];
                uint32_t b[8][2];
                #pragma unroll
                for (int mt = 0; mt < 4; mt++) {
                    int row = wm * 64 + mt * 16 + (lane & 15);
                    uint32_t addr = sa + (uint32_t)row * 128 +
                        ((uint32_t)(((kc * 2 + (lane >> 4)) ^ (row & 7))) << 4);
                    asm volatile(
                        "ldmatrix.sync.aligned.m8n8.x4.shared.b16 {%0,%1,%2,%3}, [%4];\n"
                        : "=r"(a[mt][0]), "=r"(a[mt][1]), "=r"(a[mt][2]), "=r"(a[mt][3])
                        : "r"(addr));
                }
                #pragma unroll
                for (int g = 0; g < 4; g++) {
                    int row = wn * 64 + g * 16 + (lane & 15);
                    uint32_t addr = sb + (uint32_t)row * 128 +
                        ((uint32_t)(((kc * 2 + (lane >> 4)) ^ (row & 7))) << 4);
                    uint32_t q0, q1, q2, q3;
                    asm volatile(
                        "ldmatrix.sync.aligned.m8n8.x4.shared.b16 {%0,%1,%2,%3}, [%4];\n"
                        : "=r"(q0), "=r"(q1), "=r"(q2), "=r"(q3)
                        : "r"(addr));
                    b[g * 2 + 0][0] = q0; b[g * 2 + 0][1] = q2;
                    b[g * 2 + 1][0] = q1; b[g * 2 + 1][1] = q3;
                }
                #pragma unroll
                for (int mt = 0; mt < 4; mt++) {
                    #pragma unroll
                    for (int nt = 0; nt < 8; nt++) {
                        asm volatile(
                            "mma.sync.aligned.m16n8k16.row.col.f32.f16.f16.f32 "
                            "{%0,%1,%2,%3}, {%4,%5,%6,%7}, {%8,%9}, {%0,%1,%2,%3};\n"
                            : "+f"(acc[mt][nt][0]), "+f"(acc[mt][nt][1]),
                              "+f"(acc[mt][nt][2]), "+f"(acc[mt][nt][3])
                            : "r"(a[mt][0]), "r"(a[mt][1]), "r"(a[mt][2]), "r"(a[mt][3]),
                              "r"(b[nt][0]), "r"(b[nt][1]));
                    }
                }
            }
            __syncthreads();
            if (c + 3 < 64) fillf(c + 3);
            asm volatile("cp.async.commit_group;\n" ::: "memory");
        }

        #pragma unroll
        for (int mt = 0; mt < 4; mt++) {
            int row = blockIdx.y * 256 + mh * 128 + wm * 64 + mt * 16 + (lane >> 2);
            #pragma unroll
            for (int nt = 0; nt < 8; nt++) {
                int col = blockIdx.x * 256 + wn * 64 + nt * 8 + (lane & 3) * 2;
                float b0 = bias[col];
                float b1 = bias[col + 1];
                float2 v0 = make_float2(acc[mt][nt][0] + b0, acc[mt][nt][1] + b1);
                float2 v1 = make_float2(acc[mt][nt][2] + b0, acc[mt][nt][3] + b1);
                *reinterpret_cast<float2*>(out + (size_t)row * OUT_F + col)       = v0;
                *reinterpret_cast<float2*>(out + (size_t)(row + 8) * OUT_F + col) = v1;
            }
        }
    }
#endif
}

// ---------------------------------------------------------------------------
extern "C" void kernel_launch(void* const* d_in, const int* in_sizes, int n_in,
                              void* d_out, int out_size) {
    const float* x    = (const float*)d_in[0];
    const int*   q    = (const int*)  d_in[1];
    const float* sc   = (const float*)d_in[2];
    const float* bias = (const float*)d_in[3];
    const float* A    = (const float*)d_in[4];
    const float* B    = (const float*)d_in[5];
    float*       out  = (float*)d_out;

    (void)in_sizes; (void)n_in; (void)out_size;

    cudaFuncSetAttribute(k_gemm, cudaFuncAttributeMaxDynamicSharedMemorySize,
                         SMEM_DYN);

    k_sample_shift<<<1, 32>>>();
    k_convert_x<<<(MTOT * (size_t)IN_F) / (256 * 8), 256>>>(x);
    k_build_w<<<dim3(IN_F / 512, OUT_F / 128), 256>>>(q, sc, A, B);
    k_gemm<<<dim3(OUT_F / 256, MTOT / 256), 256, SMEM_DYN>>>(bias, out);
}